// round 1
// baseline (speedup 1.0000x reference)
#include <cuda_runtime.h>

#define BSZ 16
#define SEQ 2048
#define DK  64
#define SCALE 0.125f   // 1/sqrt(64)

// Transposed Krelpos: g_Pt[t*DK + d] = Krelpos[d*SEQ + t]
__device__ float g_Pt[SEQ * DK];

__global__ void transpose_krelpos_kernel(const float* __restrict__ Kp) {
    int idx = blockIdx.x * blockDim.x + threadIdx.x;
    if (idx < SEQ * DK) {
        int t = idx / DK;
        int d = idx - t * DK;
        g_Pt[idx] = Kp[d * SEQ + t];
    }
}

// One thread = one query row. Warps 0-1: query tile p, warps 2-3: tile 31-p
// (complementary pairing => every CTA does ~SEQ key-steps of work).
__global__ __launch_bounds__(128, 3) void attn_kernel(
    const float* __restrict__ Q, const float* __restrict__ K,
    const float* __restrict__ V, float* __restrict__ Out)
{
    __shared__ float sK[64 * 64];
    __shared__ float sV[64 * 64];

    const int p   = blockIdx.x;      // 0..15
    const int b   = blockIdx.y;      // 0..15
    const int tid = threadIdx.x;     // 0..127
    const int half = tid >> 6;       // 0 = lo tile, 1 = hi tile
    const int tile = half ? (31 - p) : p;
    const int s    = tile * 64 + (tid & 63);   // this thread's query row

    // Load Q row into registers
    const float4* q4g = (const float4*)(Q + ((size_t)b * SEQ + s) * DK);
    float4 q[16];
#pragma unroll
    for (int i = 0; i < 16; i++) q[i] = q4g[i];

    float o[64];
#pragma unroll
    for (int i = 0; i < 64; i++) o[i] = 0.0f;
    float m = -1e30f;
    float l = 0.0f;

    const int tEndSelf = s + 1;                 // keys t in [0, s]
    const int ctaEnd   = 2048 - 64 * p;         // hi tile's key range bound

    const float* Kb = K + (size_t)b * SEQ * DK;
    const float* Vb = V + (size_t)b * SEQ * DK;

    for (int t0 = 0; t0 < ctaEnd; t0 += 64) {
        __syncthreads();
        // Cooperative tile load: 64x64 floats = 1024 float4, 128 threads -> 8 each
        const float4* kg = (const float4*)(Kb + (size_t)t0 * DK);
        const float4* vg = (const float4*)(Vb + (size_t)t0 * DK);
#pragma unroll
        for (int i = 0; i < 8; i++) {
            int li = i * 128 + tid;
            ((float4*)sK)[li] = kg[li];
            ((float4*)sV)[li] = vg[li];
        }
        __syncthreads();

        const int tmax = tEndSelf - t0;         // valid steps in this tile (may be <=0)
        if (tmax <= 0) continue;                // warp idles (still syncs next iter)
        const int tlim = tmax < 64 ? tmax : 64;

#pragma unroll 1
        for (int tt = 0; tt < tlim; tt++) {
            const int t = t0 + tt;
            const int c = 2047 - s + t;         // Krelpos column for this (s,t)

            const float4* kr = (const float4*)(sK + tt * 64);
            const float4* pr = (const float4*)(g_Pt + (size_t)c * DK);

            float a0 = 0.f, a1 = 0.f, a2 = 0.f, a3 = 0.f;
#pragma unroll
            for (int i = 0; i < 16; i += 4) {
                float4 k0 = kr[i + 0], p0 = pr[i + 0];
                float4 k1 = kr[i + 1], p1 = pr[i + 1];
                float4 k2 = kr[i + 2], p2 = pr[i + 2];
                float4 k3 = kr[i + 3], p3 = pr[i + 3];
                a0 = fmaf(q[i + 0].x, k0.x + p0.x, a0);
                a0 = fmaf(q[i + 0].y, k0.y + p0.y, a0);
                a0 = fmaf(q[i + 0].z, k0.z + p0.z, a0);
                a0 = fmaf(q[i + 0].w, k0.w + p0.w, a0);
                a1 = fmaf(q[i + 1].x, k1.x + p1.x, a1);
                a1 = fmaf(q[i + 1].y, k1.y + p1.y, a1);
                a1 = fmaf(q[i + 1].z, k1.z + p1.z, a1);
                a1 = fmaf(q[i + 1].w, k1.w + p1.w, a1);
                a2 = fmaf(q[i + 2].x, k2.x + p2.x, a2);
                a2 = fmaf(q[i + 2].y, k2.y + p2.y, a2);
                a2 = fmaf(q[i + 2].z, k2.z + p2.z, a2);
                a2 = fmaf(q[i + 2].w, k2.w + p2.w, a2);
                a3 = fmaf(q[i + 3].x, k3.x + p3.x, a3);
                a3 = fmaf(q[i + 3].y, k3.y + p3.y, a3);
                a3 = fmaf(q[i + 3].z, k3.z + p3.z, a3);
                a3 = fmaf(q[i + 3].w, k3.w + p3.w, a3);
            }
            float sc = ((a0 + a1) + (a2 + a3)) * SCALE;

            // Online softmax (thread-local). Rescale only when max grows.
            if (sc > m) {
                float corr = __expf(m - sc);   // exp(-inf-ish) -> 0 on first hit
                l *= corr;
#pragma unroll
                for (int i = 0; i < 64; i++) o[i] *= corr;
                m = sc;
            }
            float pe = __expf(sc - m);
            l += pe;

            const float4* vr = (const float4*)(sV + tt * 64);
#pragma unroll
            for (int i = 0; i < 16; i++) {
                float4 v = vr[i];
                o[4 * i + 0] = fmaf(pe, v.x, o[4 * i + 0]);
                o[4 * i + 1] = fmaf(pe, v.y, o[4 * i + 1]);
                o[4 * i + 2] = fmaf(pe, v.z, o[4 * i + 2]);
                o[4 * i + 3] = fmaf(pe, v.w, o[4 * i + 3]);
            }
        }
    }

    const float inv = 1.0f / l;   // l > 0: diagonal key always present
    float4* og = (float4*)(Out + ((size_t)b * SEQ + s) * DK);
#pragma unroll
    for (int i = 0; i < 16; i++) {
        float4 r;
        r.x = o[4 * i + 0] * inv;
        r.y = o[4 * i + 1] * inv;
        r.z = o[4 * i + 2] * inv;
        r.w = o[4 * i + 3] * inv;
        og[i] = r;
    }
}

extern "C" void kernel_launch(void* const* d_in, const int* in_sizes, int n_in,
                              void* d_out, int out_size) {
    const float* Q  = (const float*)d_in[0];
    const float* K  = (const float*)d_in[1];
    const float* V  = (const float*)d_in[2];
    const float* Kp = (const float*)d_in[3];
    float* Out      = (float*)d_out;

    transpose_krelpos_kernel<<<(SEQ * DK + 255) / 256, 256>>>(Kp);
    dim3 grid(16, 16);   // (query-tile pair, batch)
    attn_kernel<<<grid, 128>>>(Q, K, V, Out);
}

// round 3
// speedup vs baseline: 2.2599x; 2.2599x over previous
#include <cuda_runtime.h>
#include <cuda_bf16.h>

#define BSZ 16
#define SEQ 2048
#define DK  64
#define SCALE 0.125f   // 1/sqrt(64)

#define PROW_BYTES 144                    // 128B data + 16B pad (conflict-free)
#define PWIN_ROWS  127
#define PWIN_BYTES (PWIN_ROWS * PROW_BYTES)     // 18288
#define SMEM_BYTES (2*64*64*4 + 2*PWIN_BYTES)   // sK+sV (32KB) + 2 P windows = 69344

// Krelpos transposed + bf16: g_Pbf[t*DK + d] = bf16(Krelpos[d*SEQ + t])
__device__ __nv_bfloat16 g_Pbf[SEQ * DK];

__global__ void prep_krelpos_kernel(const float* __restrict__ Kp) {
    int idx = blockIdx.x * blockDim.x + threadIdx.x;
    if (idx < SEQ * DK) {
        int t = idx >> 6;
        int d = idx & 63;
        g_Pbf[idx] = __float2bfloat16_rn(Kp[d * SEQ + t]);
    }
}

// ---- packed f32x2 helpers ----
__device__ __forceinline__ unsigned long long pk2(float x, float y) {
    unsigned long long r;
    asm("mov.b64 %0, {%1, %2};" : "=l"(r) : "f"(x), "f"(y));
    return r;
}
__device__ __forceinline__ float2 upk(unsigned long long v) {
    float2 f;
    asm("mov.b64 {%0, %1}, %2;" : "=f"(f.x), "=f"(f.y) : "l"(v));
    return f;
}
// acc += q2 * (k2 + expand_bf16x2(pb))   [2 dims]
__device__ __forceinline__ void kp_fma2(unsigned long long& acc,
                                        unsigned long long q2,
                                        unsigned long long k2,
                                        unsigned int pb) {
    asm("{\n\t"
        ".reg .b32 lo, hi;\n\t"
        ".reg .b64 kp;\n\t"
        "prmt.b32 lo, %2, 0, 0x1044;\n\t"   // f32 bits of low bf16  (<<16)
        "prmt.b32 hi, %2, 0, 0x3244;\n\t"   // f32 bits of high bf16 (<<16)
        "mov.b64 kp, {lo, hi};\n\t"
        "add.rn.f32x2 kp, kp, %3;\n\t"
        "fma.rn.f32x2 %0, %1, kp, %0;\n\t"
        "}" : "+l"(acc) : "l"(q2), "r"(pb), "l"(k2));
}
__device__ __forceinline__ void fma2(unsigned long long& o,
                                     unsigned long long a, unsigned long long b) {
    asm("fma.rn.f32x2 %0, %1, %2, %0;" : "+l"(o) : "l"(a), "l"(b));
}
__device__ __forceinline__ void mul2(unsigned long long& o, unsigned long long a) {
    asm("mul.rn.f32x2 %0, %0, %1;" : "+l"(o) : "l"(a));
}

// One thread = one query row. Warps 0-1: tile p, warps 2-3: tile 31-p.
__global__ __launch_bounds__(128, 3) void attn_kernel(
    const float* __restrict__ Q, const float* __restrict__ K,
    const float* __restrict__ V, float* __restrict__ Out)
{
    extern __shared__ float smem[];
    float* sK = smem;                 // 64x64 f32
    float* sV = smem + 64 * 64;       // 64x64 f32
    char*  sP = (char*)(smem + 2 * 64 * 64);   // 2 windows of 127 rows x 144B (bf16)

    const int p    = blockIdx.x;      // 0..15
    const int b    = blockIdx.y;      // 0..15
    const int tid  = threadIdx.x;     // 0..127
    const int half = tid >> 6;
    const int j    = tid & 63;
    const int tileLo = p, tileHi = 31 - p;
    const int tile = half ? tileHi : tileLo;
    const int s    = tile * 64 + j;

    // Q row into packed registers
    const ulonglong2* qg = (const ulonglong2*)(Q + ((size_t)b * SEQ + s) * DK);
    unsigned long long q2[32];
#pragma unroll
    for (int i = 0; i < 16; i++) { ulonglong2 t = qg[i]; q2[2*i] = t.x; q2[2*i+1] = t.y; }

    unsigned long long o2[32];
#pragma unroll
    for (int i = 0; i < 32; i++) o2[i] = 0ull;
    float m = -1e30f, l = 0.0f;

    const int tEndSelf = s + 1;
    const int ctaEnd   = 2048 - 64 * p;   // hi tile bound (covers lo too)

    const float* Kb = K + (size_t)b * SEQ * DK;
    const float* Vb = V + (size_t)b * SEQ * DK;
    const uint4* Pg = (const uint4*)g_Pbf;          // row t at Pg + t*8 (128B rows)

    const int myPoff = half * PWIN_BYTES + (63 - j) * PROW_BYTES;

    for (int t0 = 0; t0 < ctaEnd; t0 += 64) {
        __syncthreads();
        // --- K/V tile load: 2048 float4 total, 128 threads -> 16 each
        {
            const float4* kg = (const float4*)(Kb + (size_t)t0 * DK);
            const float4* vg = (const float4*)(Vb + (size_t)t0 * DK);
#pragma unroll
            for (int i = 0; i < 8; i++) {
                int li = i * 128 + tid;
                ((float4*)sK)[li] = kg[li];
                ((float4*)sV)[li] = vg[li];
            }
        }
        // --- P window load: per half, 127 rows x 8 uint4 (guard row<=2047)
        {
            const int activeLo = (t0 <= 64 * tileLo + 63);
            const int baseLo = 1984 - 64 * tileLo + t0;
            const int baseHi = 64 * p + t0;            // = 1984 - 64*tileHi + t0
#pragma unroll
            for (int it = 0; it < 16; it++) {
                int idx = it * 128 + tid;
                if (idx >= 2 * 1016) break;
                int h   = idx >= 1016;
                int rem = idx - h * 1016;
                int r   = rem >> 3;
                int i   = rem & 7;
                if (h == 0 && !activeLo) continue;
                int srow = (h ? baseHi : baseLo) + r;
                if (srow > 2047) continue;
                *(uint4*)(sP + h * PWIN_BYTES + r * PROW_BYTES + i * 16) = Pg[srow * 8 + i];
            }
        }
        __syncthreads();

        const int tmax = tEndSelf - t0;
        if (tmax <= 0) continue;
        const int tlim = tmax < 64 ? tmax : 64;

#pragma unroll 1
        for (int tt = 0; tt < tlim; tt++) {
            const ulonglong2* kr = (const ulonglong2*)(sK + tt * 64);
            const uint4* pr = (const uint4*)(sP + myPoff + tt * PROW_BYTES);

            unsigned long long a0 = 0, a1 = 0, a2 = 0, a3 = 0;
#pragma unroll
            for (int i = 0; i < 8; i++) {
                uint4 pu = pr[i];
                ulonglong2 ka = kr[2 * i];
                ulonglong2 kb = kr[2 * i + 1];
                kp_fma2(a0, q2[4 * i + 0], ka.x, pu.x);
                kp_fma2(a1, q2[4 * i + 1], ka.y, pu.y);
                kp_fma2(a2, q2[4 * i + 2], kb.x, pu.z);
                kp_fma2(a3, q2[4 * i + 3], kb.y, pu.w);
            }
            float2 f0 = upk(a0), f1 = upk(a1), f2 = upk(a2), f3 = upk(a3);
            float sc = (((f0.x + f0.y) + (f1.x + f1.y)) +
                        ((f2.x + f2.y) + (f3.x + f3.y))) * SCALE;

            if (sc > m) {
                float corr = __expf(m - sc);
                l *= corr;
                unsigned long long c2 = pk2(corr, corr);
#pragma unroll
                for (int i = 0; i < 32; i++) mul2(o2[i], c2);
                m = sc;
            }
            float pe = __expf(sc - m);
            l += pe;
            unsigned long long pe2 = pk2(pe, pe);

            const ulonglong2* vr = (const ulonglong2*)(sV + tt * 64);
#pragma unroll
            for (int i = 0; i < 16; i++) {
                ulonglong2 v = vr[i];
                fma2(o2[2 * i + 0], pe2, v.x);
                fma2(o2[2 * i + 1], pe2, v.y);
            }
        }
    }

    const float inv = 1.0f / l;
    float4* og = (float4*)(Out + ((size_t)b * SEQ + s) * DK);
#pragma unroll
    for (int i = 0; i < 16; i++) {
        float2 a = upk(o2[2 * i]), c = upk(o2[2 * i + 1]);
        float4 r;
        r.x = a.x * inv; r.y = a.y * inv; r.z = c.x * inv; r.w = c.y * inv;
        og[i] = r;
    }
}

extern "C" void kernel_launch(void* const* d_in, const int* in_sizes, int n_in,
                              void* d_out, int out_size) {
    const float* Q  = (const float*)d_in[0];
    const float* K  = (const float*)d_in[1];
    const float* V  = (const float*)d_in[2];
    const float* Kp = (const float*)d_in[3];
    float* Out      = (float*)d_out;

    cudaFuncSetAttribute(attn_kernel, cudaFuncAttributeMaxDynamicSharedMemorySize,
                         SMEM_BYTES);

    prep_krelpos_kernel<<<(SEQ * DK + 255) / 256, 256>>>(Kp);
    dim3 grid(16, 16);
    attn_kernel<<<grid, 128, SMEM_BYTES>>>(Q, K, V, Out);
}